// round 11
// baseline (speedup 1.0000x reference)
#include <cuda_runtime.h>
#include <cstdint>
#include <cstddef>

using ull = unsigned long long;

#define THREADS 576
#define NCH     256
#define CK      16
#define NSTAGE  (NCH / CK)          // 16
#define H       64
#define W       64
#define TH      16
#define TW      32
#define YROWS   (TH + 8)            // 24
#define YSTR    44                  // floats; conflict-free, rows 16B-aligned
#define XSTR    36
#define YS_BUF  (CK * YROWS * YSTR) // 16896 floats
#define XS_BUF  (CK * TH * XSTR)    // 9216 floats
#define BUF_FLOATS (YS_BUF + XS_BUF)        // 26112
#define BUF_BYTES  (BUF_FLOATS * 4)
#define SMEM_BYTES (2 * BUF_BYTES)          // 208896 B (2-stage pipeline)

#define YCH_B   (YROWS * YSTR * 4)  // 4224 B per channel of y
#define XCH_B   (TH * XSTR * 4)     // 2304 B per channel of x

#define NYV (CK * YROWS * 10)       // 3840 vec4 y-loads per stage
#define NXV (CK * TH * 8)           // 2048 vec4 x-loads per stage

// ---- async copy helpers (zfill gives the zero-padded halo for free) ----
__device__ __forceinline__ void cp16(uint32_t dst, const float* src, int ok) {
    asm volatile("cp.async.cg.shared.global [%0], [%1], 16, %2;\n"
                 :: "r"(dst), "l"(src), "r"(ok ? 16 : 0));
}
__device__ __forceinline__ void cp_commit() { asm volatile("cp.async.commit_group;\n"); }
__device__ __forceinline__ void cp_wait0()  { asm volatile("cp.async.wait_group 0;\n"); }

// ---- packed f32x2 math (FFMA2 is PTX-only on sm_103a) ----
__device__ __forceinline__ void fma2(ull& acc, ull a, ull b) {
    asm("fma.rn.f32x2 %0, %1, %2, %0;" : "+l"(acc) : "l"(a), "l"(b));
}
__device__ __forceinline__ ull mul2(ull a, ull b) {
    ull d;
    asm("mul.rn.f32x2 %0, %1, %2;" : "=l"(d) : "l"(a), "l"(b));
    return d;
}
__device__ __forceinline__ ull shft(ull lo, ull hi) {
    return (lo >> 32) | (hi << 32);   // odd-offset f32 pair {lo.hi, hi.lo}
}
// 16B shared load as two u64 (adjacent f32 pairs)
#define LDSV2(a, b, addr) \
    asm volatile("ld.shared.v2.u64 {%0, %1}, [%2];" : "=l"(a), "=l"(b) : "r"(addr))

__global__ __launch_bounds__(THREADS, 1)
void corr_kernel(const float* __restrict__ xg, const float* __restrict__ yg,
                 float* __restrict__ out) {
    extern __shared__ float sm[];

    const int tid  = threadIdx.x;
    const int bb   = blockIdx.x >> 3;          // batch
    const int tile = blockIdx.x & 7;           // 4 row-tiles x 2 col-tiles
    const int i0   = (tile >> 1) * TH;
    const int j0   = (tile & 1) * TW;

    const int wid  = tid >> 5;
    const int lane = tid & 31;
    const int di   = (wid < 9) ? wid : wid - 9;   // displacement row 0..8
    const int half = (wid < 9) ? 0 : 1;
    const int gi   = half * 8 + (lane >> 2);      // pixel row within tile 0..15
    const int jl   = (lane & 3) * 8;              // 8-wide pixel strip start

    const uint32_t sbase = (uint32_t)__cvta_generic_to_shared(sm);

    // acc[dj*4 + m] = packed pixels (jl+2m, jl+2m+1) at displacement (di, dj)
    ull acc[36];
#pragma unroll
    for (int k = 0; k < 36; k++) acc[k] = 0ULL;

    // ---------------- stage loader (cp.async) ----------------
    auto load_stage = [&](int s, int buf) {
        const uint32_t yb = sbase + (uint32_t)buf * BUF_BYTES;
        const uint32_t xb = yb + (uint32_t)YS_BUF * 4u;
        const float* ygs = yg + ((size_t)(bb * NCH + s * CK)) * (H * W);
        const float* xgs = xg + ((size_t)(bb * NCH + s * CK)) * (H * W);
#pragma unroll
        for (int k = 0; k < 7; k++) {
            if (k < 6 || tid < NYV - 6 * THREADS) {
                int idx = tid + k * THREADS;
                int cc  = idx / (YROWS * 10);
                int rem = idx - cc * (YROWS * 10);
                int r   = rem / 10;
                int q   = rem - r * 10;
                int gr  = i0 + r - 4;
                int gc  = j0 - 4 + 4 * q;
                int ok  = (gr >= 0) & (gr < H) & (gc >= 0) & (gc < W);
                const float* src = ygs + ((cc * H + (ok ? gr : 0)) * W + (ok ? gc : 0));
                cp16(yb + (uint32_t)((cc * YROWS + r) * YSTR + 4 * q) * 4u, src, ok);
            }
        }
#pragma unroll
        for (int k = 0; k < 4; k++) {
            if (k < 3 || tid < NXV - 3 * THREADS) {
                int idx = tid + k * THREADS;
                int cc  = idx >> 7;            // / (TH*8)
                int r   = (idx >> 3) & 15;
                int q   = idx & 7;
                const float* src = xgs + ((cc * H + i0 + r) * W + j0 + 4 * q);
                cp16(xb + (uint32_t)((cc * TH + r) * XSTR + 4 * q) * 4u, src, 1);
            }
        }
        cp_commit();
    };

    // ---------------- 2-stage pipeline ----------------
    load_stage(0, 0);

    const uint32_t yoff = (uint32_t)((gi + di) * YSTR + jl) * 4u;
    const uint32_t xoff = (uint32_t)(YS_BUF + gi * XSTR + jl) * 4u;

    int buf = 0;
#pragma unroll 1
    for (int s = 0; s < NSTAGE; s++) {
        cp_wait0();          // stage s landed
        __syncthreads();     // visible to all; prior stage's reads complete
        if (s + 1 < NSTAGE) load_stage(s + 1, buf ^ 1);

        const uint32_t ya = sbase + (uint32_t)buf * BUF_BYTES + yoff;
        const uint32_t xa = sbase + (uint32_t)buf * BUF_BYTES + xoff;

        // preload channel 0 of this stage
        ull w[8], xp[4], sp;
        LDSV2(w[0], w[1], ya);      LDSV2(w[2], w[3], ya + 16);
        LDSV2(w[4], w[5], ya + 32); LDSV2(w[6], w[7], ya + 48);
        LDSV2(xp[0], xp[1], xa);    LDSV2(xp[2], xp[3], xa + 16);

        // o-major FMA schedule: o = 2m + dj. Each w/x slot is reloaded with
        // the NEXT channel's data immediately after its last use, so every
        // shared load leads its first consumer by ~25-40 instructions.
#pragma unroll
        for (int cc = 0; cc < CK; cc++) {
            const bool pf = (cc + 1 < CK);
            const uint32_t yn = ya + (uint32_t)(cc + 1) * YCH_B;
            const uint32_t xn = xa + (uint32_t)(cc + 1) * XCH_B;

            // o=0
            fma2(acc[0], xp[0], w[0]);
            // o=1
            sp = shft(w[0], w[1]);
            fma2(acc[4], xp[0], sp);
            // o=2
            fma2(acc[8], xp[0], w[1]);  fma2(acc[1], xp[1], w[1]);
            // o=3
            sp = shft(w[1], w[2]);
            fma2(acc[12], xp[0], sp);   fma2(acc[5], xp[1], sp);
            if (pf) LDSV2(w[0], w[1], yn);            // y vec0 dead
            // o=4
            fma2(acc[16], xp[0], w[2]); fma2(acc[9], xp[1], w[2]);
            fma2(acc[2],  xp[2], w[2]);
            // o=5
            sp = shft(w[2], w[3]);
            fma2(acc[20], xp[0], sp);   fma2(acc[13], xp[1], sp);
            fma2(acc[6],  xp[2], sp);
            // o=6
            fma2(acc[24], xp[0], w[3]); fma2(acc[17], xp[1], w[3]);
            fma2(acc[10], xp[2], w[3]); fma2(acc[3],  xp[3], w[3]);
            // o=7
            sp = shft(w[3], w[4]);
            fma2(acc[28], xp[0], sp);   fma2(acc[21], xp[1], sp);
            fma2(acc[14], xp[2], sp);   fma2(acc[7],  xp[3], sp);
            if (pf) LDSV2(w[2], w[3], yn + 16);       // y vec1 dead
            // o=8
            fma2(acc[32], xp[0], w[4]); fma2(acc[25], xp[1], w[4]);
            fma2(acc[18], xp[2], w[4]); fma2(acc[11], xp[3], w[4]);
            // o=9  (xp[0] dead)
            sp = shft(w[4], w[5]);
            fma2(acc[29], xp[1], sp);   fma2(acc[22], xp[2], sp);
            fma2(acc[15], xp[3], sp);
            // o=10
            fma2(acc[33], xp[1], w[5]); fma2(acc[26], xp[2], w[5]);
            fma2(acc[19], xp[3], w[5]);
            if (pf) LDSV2(xp[0], xp[1], xn);          // x vec0 dead
            // o=11
            sp = shft(w[5], w[6]);
            fma2(acc[30], xp[2], sp);   fma2(acc[23], xp[3], sp);
            if (pf) LDSV2(w[4], w[5], yn + 32);       // y vec2 dead
            // o=12
            fma2(acc[34], xp[2], w[6]); fma2(acc[27], xp[3], w[6]);
            // o=13
            sp = shft(w[6], w[7]);
            fma2(acc[31], xp[3], sp);
            // o=14
            fma2(acc[35], xp[3], w[7]);
            if (pf) { LDSV2(w[6], w[7], yn + 48);     // y vec3 dead
                      LDSV2(xp[2], xp[3], xn + 16); } // x vec1 dead
        }

        buf ^= 1;
    }

    // ---------------- epilogue: scale by 1/C, store ----------------
    const uint32_t su = __float_as_uint(1.0f / 256.0f);
    const ull scl = ((ull)su << 32) | su;
#pragma unroll
    for (int dj = 0; dj < 9; dj++) {
        float* op = out + (((size_t)bb * 81 + di * 9 + dj) * H + (i0 + gi)) * W
                        + j0 + jl;
        ulonglong2 v0, v1;
        v0.x = mul2(acc[dj * 4 + 0], scl);
        v0.y = mul2(acc[dj * 4 + 1], scl);
        v1.x = mul2(acc[dj * 4 + 2], scl);
        v1.y = mul2(acc[dj * 4 + 3], scl);
        ((ulonglong2*)op)[0] = v0;
        ((ulonglong2*)op)[1] = v1;
    }
}

extern "C" void kernel_launch(void* const* d_in, const int* in_sizes, int n_in,
                              void* d_out, int out_size) {
    (void)in_sizes; (void)n_in; (void)out_size;
    const float* x = (const float*)d_in[0];
    const float* y = (const float*)d_in[1];
    cudaFuncSetAttribute(corr_kernel, cudaFuncAttributeMaxDynamicSharedMemorySize,
                         SMEM_BYTES);
    corr_kernel<<<16 * 8, THREADS, SMEM_BYTES>>>(x, y, (float*)d_out);
}